// round 15
// baseline (speedup 1.0000x reference)
#include <cuda_runtime.h>
#include <cuda_fp16.h>
#include <math.h>
#include <stdint.h>

#define SEQ    2048
#define HID    2048
#define NHEADS 16
#define DH     128
#define ATT_SCALE 0.08838834764831845f   // 1/sqrt(128)

// ---------------- scratch (device globals: allocation-free) ----------------
__device__ float g_q[SEQ * HID];
__device__ float g_k[SEQ * HID];
__device__ float g_o[SEQ * HID];
__device__ float g_rope[SEQ * 64 * 2];      // cos/sin table
__device__ __half g_xhi[SEQ * HID];         // x / attn
__device__ __half g_whi[4 * HID * HID];     // weights
__device__ __half g_qhi[SEQ * HID];
__device__ __half g_khi[SEQ * HID];
__device__ __half g_vhi[SEQ * HID];

// ====================================================================
// common helpers
// ====================================================================
__device__ __forceinline__ uint32_t smem_u32(const void* p) {
    uint32_t a;
    asm("{ .reg .u64 t; cvta.to.shared.u64 t, %1; cvt.u32.u64 %0, t; }"
        : "=r"(a) : "l"(p));
    return a;
}

__device__ __forceinline__ uint32_t pack2h(__half a, __half b) {
    return (uint32_t)__half_as_ushort(a) |
           ((uint32_t)__half_as_ushort(b) << 16);
}

#define LDSM4(d0, d1, d2, d3, addr)                                        \
    asm volatile("ldmatrix.sync.aligned.m8n8.x4.shared.b16 "               \
                 "{%0,%1,%2,%3}, [%4];"                                    \
                 : "=r"(d0), "=r"(d1), "=r"(d2), "=r"(d3) : "r"(addr))

#define LDSM4T(d0, d1, d2, d3, addr)                                       \
    asm volatile("ldmatrix.sync.aligned.m8n8.x4.trans.shared.b16 "         \
                 "{%0,%1,%2,%3}, [%4];"                                    \
                 : "=r"(d0), "=r"(d1), "=r"(d2), "=r"(d3) : "r"(addr))

#define MMA_F16(acc, a, b)                                                 \
    asm volatile("mma.sync.aligned.m16n8k16.row.col.f32.f16.f16.f32 "      \
                 "{%0,%1,%2,%3}, {%4,%5,%6,%7}, {%8,%9}, {%0,%1,%2,%3};"   \
                 : "+f"((acc)[0]), "+f"((acc)[1]), "+f"((acc)[2]),         \
                   "+f"((acc)[3])                                          \
                 : "r"((a)[0]), "r"((a)[1]), "r"((a)[2]), "r"((a)[3]),     \
                   "r"((b)[0]), "r"((b)[1]))

#define CPA16(dst, src)                                                    \
    asm volatile("cp.async.cg.shared.global [%0], [%1], 16;"               \
                 :: "r"(dst), "l"(src))

// ====================================================================
// fp32 -> fp16 convert for x + 4 weights, plus rope table (y==5).
// ====================================================================
__global__ __launch_bounds__(256) void split6_kernel(
    const float* __restrict__ x,
    const float* __restrict__ wq, const float* __restrict__ wk,
    const float* __restrict__ wv, const float* __restrict__ wo,
    __half* __restrict__ xhi, __half* __restrict__ whi,
    float* __restrict__ rtab, int n4)
{
    const size_t W = (size_t)HID * HID;
    if (blockIdx.y == 5) {
        const int idx = blockIdx.x * 256 + threadIdx.x;
        if (idx < SEQ * 64) {
            const int s = idx >> 6;
            const int i = idx & 63;
            const float invf = (float)pow(10000.0, -(double)(2 * i) / 128.0);
            const float ang  = (float)s * invf;
            rtab[idx * 2]     = (float)cos((double)ang);
            rtab[idx * 2 + 1] = (float)sin((double)ang);
        }
        return;
    }
    const float* in;
    __half* hi;
    switch (blockIdx.y) {
        case 0:  in = x;  hi = xhi;         break;
        case 1:  in = wq; hi = whi;         break;
        case 2:  in = wk; hi = whi + W;     break;
        case 3:  in = wv; hi = whi + 2 * W; break;
        default: in = wo; hi = whi + 3 * W; break;
    }
    const int stride = gridDim.x * 256;
#pragma unroll
    for (int j = 0; j < 4; ++j) {
        const int i = blockIdx.x * 256 + threadIdx.x + j * stride;
        if (i < n4) {
            const float4 v = *(const float4*)(in + (size_t)i * 4);
            uint2 ph;
            ph.x = pack2h(__float2half_rn(v.x), __float2half_rn(v.y));
            ph.y = pack2h(__float2half_rn(v.z), __float2half_rn(v.w));
            *(uint2*)(hi + (size_t)i * 4) = ph;
        }
    }
}

// ====================================================================
// RoPE + fp16 convert for q,k (reads precomputed table)
// ====================================================================
__global__ __launch_bounds__(1024) void rope_split_kernel(
    const float* __restrict__ q, const float* __restrict__ k,
    const float* __restrict__ tab,
    __half* __restrict__ qhi, __half* __restrict__ khi)
{
    const int s = blockIdx.x;
    const int t = threadIdx.x;
    const int h = t >> 6;
    const int i = t & 63;

    const float c  = tab[(s * 64 + i) * 2];
    const float sn = tab[(s * 64 + i) * 2 + 1];

    const int base = s * HID + h * DH + i;

    float a = q[base], b = q[base + 64];
    qhi[base]      = __float2half_rn(a * c - b * sn);
    qhi[base + 64] = __float2half_rn(b * c + a * sn);

    a = k[base];  b = k[base + 64];
    khi[base]      = __float2half_rn(a * c - b * sn);
    khi[base + 64] = __float2half_rn(b * c + a * sn);
}

// ====================================================================
// Pure fp16 persistent GEMM, BK=64, 128 threads (4 warps, 2x2),
// warp tile 64x64 (ldsm:MMA = 0.25), 2 CTAs/SM, grid = 296 CTAs.
// z==2 with vmode emits fp16 V; else fp32+bias.
// ====================================================================
#define GBM 128
#define GBN 128
#define GBK 64
#define GKIT (HID / GBK)             // 32
#define PITCH 40
#define TILE_B (128 * PITCH * 2)     // 10240 (one 128x32-half sub-tile)
#define OFF_A 0
#define OFF_B (2 * TILE_B)
#define STAGE_B (4 * TILE_B)         // 40960
#define GEMM_SMEM (2 * STAGE_B)      // 81920
#define GEMM_GRID 296

__global__ __launch_bounds__(128, 2) void gemm_f16(
    const __half* __restrict__ Ah, const __half* __restrict__ Wbase,
    const float* __restrict__ b0, const float* __restrict__ b1,
    const float* __restrict__ b2,
    float* __restrict__ C0, float* __restrict__ C1,
    __half* __restrict__ Vh, int ntiles, int vmode)
{
    extern __shared__ char sm[];
    const uint32_t sbase = smem_u32(sm);

    const int tid  = threadIdx.x;
    const int lane = tid & 31;
    const int wid  = tid >> 5;
    const int wm   = wid & 1;        // M half (64 rows)
    const int wn   = wid >> 1;       // N half (64 cols)

    const uint32_t sdst = (uint32_t)(tid * (PITCH * 2));  // one row per thread

    for (int tile = blockIdx.x; tile < ntiles; tile += GEMM_GRID) {
        const int z   = tile >> 8;
        const int rem = tile & 255;
        const int bm = (rem >> 4) * GBM;
        const int bn = (rem & 15) * GBN;

        const __half* Bh = Wbase + (size_t)z * HID * HID;
        const float* bias = (z == 0) ? b0 : (z == 1 ? b1 : b2);

        const __half* pA = Ah + (size_t)(bm + tid) * HID;
        const __half* pB = Bh + (size_t)(bn + tid) * HID;

        float acc[4][8][4];
#pragma unroll
        for (int mi = 0; mi < 4; ++mi)
#pragma unroll
            for (int nj = 0; nj < 8; ++nj)
#pragma unroll
                for (int c = 0; c < 4; ++c) acc[mi][nj][c] = 0.f;

        auto load_stage = [&](int kt, int buf) {
            const int k0 = kt * GBK;
            const uint32_t s = sbase + buf * STAGE_B + sdst;
#pragma unroll
            for (int ch = 0; ch < 2; ++ch)
#pragma unroll
                for (int p = 0; p < 4; ++p) {     // FULL 64B row per sub-tile
                    CPA16(s + OFF_A + ch * TILE_B + p * 16,
                          pA + k0 + ch * 32 + p * 8);
                    CPA16(s + OFF_B + ch * TILE_B + p * 16,
                          pB + k0 + ch * 32 + p * 8);
                }
        };

        load_stage(0, 0);
        asm volatile("cp.async.commit_group;");

        int buf = 0;
        for (int kt = 0; kt < GKIT; ++kt) {
            asm volatile("cp.async.wait_group 0;");
            __syncthreads();
            if (kt + 1 < GKIT) {
                load_stage(kt + 1, buf ^ 1);
                asm volatile("cp.async.commit_group;");
            }

            const uint32_t sS = sbase + buf * STAGE_B;

#pragma unroll
            for (int kk = 0; kk < 4; ++kk) {
                const uint32_t sA = sS + OFF_A + (kk >> 1) * TILE_B;
                const uint32_t sB = sS + OFF_B + (kk >> 1) * TILE_B;
                const int ksub = kk & 1;
                uint32_t a[4][4];
                const int r16 = lane & 15;
                const int ksel = lane >> 4;
#pragma unroll
                for (int mi = 0; mi < 4; ++mi) {
                    const uint32_t off =
                        (uint32_t)((wm * 64 + mi * 16 + r16) * (PITCH * 2) +
                                   (ksub * 2 + ksel) * 16);
                    LDSM4(a[mi][0], a[mi][1], a[mi][2], a[mi][3], sA + off);
                }
                const int q  = lane >> 3;
                const int rr = lane & 7;
#pragma unroll
                for (int a2 = 0; a2 < 4; ++a2) {
                    uint32_t bh[4];
                    const int row = wn * 64 + a2 * 16 + (q >> 1) * 8 + rr;
                    const uint32_t off =
                        (uint32_t)(row * (PITCH * 2) + (ksub * 2 + (q & 1)) * 16);
                    LDSM4(bh[0], bh[1], bh[2], bh[3], sB + off);
#pragma unroll
                    for (int mi = 0; mi < 4; ++mi) {
                        MMA_F16(acc[mi][a2 * 2],     a[mi], bh);
                        MMA_F16(acc[mi][a2 * 2 + 1], a[mi], bh + 2);
                    }
                }
            }
            buf ^= 1;
        }

        const int trow = lane >> 2;
        const int tcol = (lane & 3) * 2;
        if (vmode && z == 2) {
#pragma unroll
            for (int mi = 0; mi < 4; ++mi) {
                const int r = bm + wm * 64 + mi * 16 + trow;
#pragma unroll
                for (int nj = 0; nj < 8; ++nj) {
                    const int c = bn + wn * 64 + nj * 8 + tcol;
                    const float bx = bias[c], by = bias[c + 1];
                    *(uint32_t*)(Vh + (size_t)r * HID + c) =
                        pack2h(__float2half_rn(acc[mi][nj][0] + bx),
                               __float2half_rn(acc[mi][nj][1] + by));
                    *(uint32_t*)(Vh + (size_t)(r + 8) * HID + c) =
                        pack2h(__float2half_rn(acc[mi][nj][2] + bx),
                               __float2half_rn(acc[mi][nj][3] + by));
                }
            }
        } else {
            float* C = (z == 0) ? C0 : C1;
#pragma unroll
            for (int mi = 0; mi < 4; ++mi) {
                const int r = bm + wm * 64 + mi * 16 + trow;
#pragma unroll
                for (int nj = 0; nj < 8; ++nj) {
                    const int c = bn + wn * 64 + nj * 8 + tcol;
                    const float bx = bias[c], by = bias[c + 1];
                    float2 o;
                    o.x = acc[mi][nj][0] + bx; o.y = acc[mi][nj][1] + by;
                    *(float2*)(C + (size_t)r * HID + c) = o;
                    o.x = acc[mi][nj][2] + bx; o.y = acc[mi][nj][3] + by;
                    *(float2*)(C + (size_t)(r + 8) * HID + c) = o;
                }
            }
        }
    }
}

// ====================================================================
// Flash attention, pure fp16, 64-row q tiles, 128 threads (4 warps).
// Single-sync pipeline, long CTAs first. Writes attn fp16.
// ====================================================================
#define FP_B 272
#define QTILE_FB (64 * FP_B)         // 17408
#define KVTILE_FB (64 * FP_B)        // 17408
#define FKV0 QTILE_FB
#define FKSTG (2 * KVTILE_FB)        // 34816
#define FLASH_SMEM (FKV0 + 2 * FKSTG)   // 87040

__global__ __launch_bounds__(128) void flash_tc(
    const __half* __restrict__ qhi, const __half* __restrict__ khi,
    const __half* __restrict__ vhi, __half* __restrict__ Oh)
{
    extern __shared__ char sm[];
    const uint32_t sb = smem_u32(sm);
    const int h  = blockIdx.y;
    const int qb = gridDim.x - 1 - blockIdx.x;   // long CTAs first
    const int q0 = qb * 64;
    const int tid = threadIdx.x, lane = tid & 31, wm = tid >> 5;

    {
        const __half* ph = qhi + (size_t)q0 * HID + h * DH;
#pragma unroll
        for (int i = 0; i < 8; ++i) {
            const int idx = tid + i * 128, row = idx >> 4, c = idx & 15;
            CPA16(sb + (uint32_t)(row * FP_B + c * 16),
                  ph + (size_t)row * HID + c * 8);
        }
    }

    auto load_kv = [&](int t, int b) {
        const int j0 = t * 64;
        const uint32_t s = sb + FKV0 + b * FKSTG;
#pragma unroll
        for (int i = 0; i < 8; ++i) {
            const int idx = tid + i * 128, row = idx >> 4, c = idx & 15;
            const uint32_t d = (uint32_t)(row * FP_B + c * 16);
            const size_t g = (size_t)(j0 + row) * HID + h * DH + c * 8;
            CPA16(s + d,             khi + g);
            CPA16(s + KVTILE_FB + d, vhi + g);
        }
    };

    load_kv(0, 0);
    asm volatile("cp.async.commit_group;");

    float o[16][4];
#pragma unroll
    for (int f = 0; f < 16; ++f)
#pragma unroll
        for (int c = 0; c < 4; ++c) o[f][c] = 0.f;
    float m0 = -1e30f, m1 = -1e30f, l0 = 0.f, l1 = 0.f;

    const int ntiles = qb + 1;
    int buf = 0;
    for (int t = 0; t < ntiles; ++t) {
        asm volatile("cp.async.wait_group 0;");
        __syncthreads();
        if (t + 1 < ntiles) {
            load_kv(t + 1, buf ^ 1);
            asm volatile("cp.async.commit_group;");
        }

        const int j0 = t * 64;
        const uint32_t skh = sb + FKV0 + buf * FKSTG;
        const uint32_t svh = skh + KVTILE_FB;

        {
            float sc[8][4];
#pragma unroll
            for (int nj = 0; nj < 8; ++nj)
#pragma unroll
                for (int c = 0; c < 4; ++c) sc[nj][c] = 0.f;

            const int r16 = lane & 15, ksel = lane >> 4;
            const int qq = lane >> 3, rr = lane & 7;
#pragma unroll
            for (int kk = 0; kk < 8; ++kk) {
                uint32_t ah[4];
                const uint32_t aoff =
                    (uint32_t)((wm * 16 + r16) * FP_B + (kk * 2 + ksel) * 16);
                LDSM4(ah[0], ah[1], ah[2], ah[3], sb + aoff);
#pragma unroll
                for (int a2 = 0; a2 < 4; ++a2) {
                    uint32_t bh[4];
                    const uint32_t boff =
                        (uint32_t)((a2 * 16 + (qq >> 1) * 8 + rr) * FP_B +
                                   (kk * 2 + (qq & 1)) * 16);
                    LDSM4(bh[0], bh[1], bh[2], bh[3], skh + boff);
                    MMA_F16(sc[a2 * 2],     ah, bh);
                    MMA_F16(sc[a2 * 2 + 1], ah, bh + 2);
                }
            }

            const int r0g = q0 + wm * 16 + (lane >> 2);
            const bool needMask = (j0 + 63 > q0 + wm * 16);
#pragma unroll
            for (int nj = 0; nj < 8; ++nj) {
                const int c0 = j0 + nj * 8 + (lane & 3) * 2;
                sc[nj][0] *= ATT_SCALE; sc[nj][1] *= ATT_SCALE;
                sc[nj][2] *= ATT_SCALE; sc[nj][3] *= ATT_SCALE;
                if (needMask) {
                    if (c0     > r0g)     sc[nj][0] = -1e30f;
                    if (c0 + 1 > r0g)     sc[nj][1] = -1e30f;
                    if (c0     > r0g + 8) sc[nj][2] = -1e30f;
                    if (c0 + 1 > r0g + 8) sc[nj][3] = -1e30f;
                }
            }

            float mx0 = -1e30f, mx1 = -1e30f;
#pragma unroll
            for (int nj = 0; nj < 8; ++nj) {
                mx0 = fmaxf(mx0, fmaxf(sc[nj][0], sc[nj][1]));
                mx1 = fmaxf(mx1, fmaxf(sc[nj][2], sc[nj][3]));
            }
            mx0 = fmaxf(mx0, __shfl_xor_sync(0xffffffffu, mx0, 1));
            mx0 = fmaxf(mx0, __shfl_xor_sync(0xffffffffu, mx0, 2));
            mx1 = fmaxf(mx1, __shfl_xor_sync(0xffffffffu, mx1, 1));
            mx1 = fmaxf(mx1, __shfl_xor_sync(0xffffffffu, mx1, 2));
            const float mn0 = fmaxf(m0, mx0), mn1 = fmaxf(m1, mx1);
            const float al0 = __expf(m0 - mn0), al1 = __expf(m1 - mn1);
            float rs0 = 0.f, rs1 = 0.f;
#pragma unroll
            for (int nj = 0; nj < 8; ++nj) {
                sc[nj][0] = __expf(sc[nj][0] - mn0);
                sc[nj][1] = __expf(sc[nj][1] - mn0);
                sc[nj][2] = __expf(sc[nj][2] - mn1);
                sc[nj][3] = __expf(sc[nj][3] - mn1);
                rs0 += sc[nj][0] + sc[nj][1];
                rs1 += sc[nj][2] + sc[nj][3];
            }
            rs0 += __shfl_xor_sync(0xffffffffu, rs0, 1);
            rs0 += __shfl_xor_sync(0xffffffffu, rs0, 2);
            rs1 += __shfl_xor_sync(0xffffffffu, rs1, 1);
            rs1 += __shfl_xor_sync(0xffffffffu, rs1, 2);
            l0 = l0 * al0 + rs0; l1 = l1 * al1 + rs1;
            m0 = mn0; m1 = mn1;
#pragma unroll
            for (int f = 0; f < 16; ++f) {
                o[f][0] *= al0; o[f][1] *= al0;
                o[f][2] *= al1; o[f][3] *= al1;
            }

            uint32_t pfh[4][4];
#pragma unroll
            for (int tp = 0; tp < 4; ++tp) {
                const float* f0 = sc[2 * tp];
                const float* f1 = sc[2 * tp + 1];
#pragma unroll
                for (int half = 0; half < 2; ++half) {
                    const float a0 = half ? f1[0] : f0[0];
                    const float a1 = half ? f1[1] : f0[1];
                    const float a2 = half ? f1[2] : f0[2];
                    const float a3 = half ? f1[3] : f0[3];
                    pfh[tp][half * 2] =
                        pack2h(__float2half_rn(a0), __float2half_rn(a1));
                    pfh[tp][half * 2 + 1] =
                        pack2h(__float2half_rn(a2), __float2half_rn(a3));
                }
            }

            const int g = lane >> 3;
#pragma unroll
            for (int ks = 0; ks < 4; ++ks) {
                uint32_t vh[16][2];
                const int jrow = ks * 16 + (g & 1) * 8 + (lane & 7);
                const uint32_t cb = (uint32_t)((g >> 1) * 16);
#pragma unroll
                for (int n0 = 0; n0 < 8; ++n0) {
                    const uint32_t boff = (uint32_t)(jrow * FP_B + n0 * 32) + cb;
                    LDSM4T(vh[n0 * 2][0], vh[n0 * 2][1],
                           vh[n0 * 2 + 1][0], vh[n0 * 2 + 1][1], svh + boff);
                }
#pragma unroll
                for (int nf = 0; nf < 16; ++nf)
                    MMA_F16(o[nf], pfh[ks], vh[nf]);
            }
        }
        buf ^= 1;
    }

    const float i0 = 1.f / l0, i1 = 1.f / l1;
    const int r0g = q0 + wm * 16 + (lane >> 2);
#pragma unroll
    for (int nf = 0; nf < 16; ++nf) {
        const int col = h * DH + nf * 8 + (lane & 3) * 2;
        *(uint32_t*)(Oh + (size_t)r0g * HID + col) =
            pack2h(__float2half_rn(o[nf][0] * i0),
                   __float2half_rn(o[nf][1] * i0));
        *(uint32_t*)(Oh + (size_t)(r0g + 8) * HID + col) =
            pack2h(__float2half_rn(o[nf][2] * i1),
                   __float2half_rn(o[nf][3] * i1));
    }
}

// ====================================================================
// Residual + LayerNorm.
// ====================================================================
__device__ __forceinline__ float block_sum256(float v, float* red)
{
    __syncthreads();
    const int lane = threadIdx.x & 31;
    const int wp   = threadIdx.x >> 5;
#pragma unroll
    for (int o = 16; o; o >>= 1) v += __shfl_xor_sync(0xffffffffu, v, o);
    if (lane == 0) red[wp] = v;
    __syncthreads();
    if (wp == 0) {
        v = (lane < 8) ? red[lane] : 0.f;
#pragma unroll
        for (int o = 4; o; o >>= 1) v += __shfl_xor_sync(0xffffffffu, v, o);
        if (lane == 0) red[0] = v;
    }
    __syncthreads();
    return red[0];
}

__global__ __launch_bounds__(256) void ln_kernel(
    const float* __restrict__ O, const float* __restrict__ X,
    const float* __restrict__ w, const float* __restrict__ b,
    float* __restrict__ out)
{
    __shared__ float row[HID];
    __shared__ float red[8];
    const int s = blockIdx.x;
    const int tid = threadIdx.x;

    float lsum = 0.f;
    for (int c = tid * 4; c < HID; c += 1024) {
        const float4 o4 = *(const float4*)(O + s * HID + c);
        const float4 x4 = *(const float4*)(X + s * HID + c);
        float4 r;
        r.x = o4.x + x4.x; r.y = o4.y + x4.y;
        r.z = o4.z + x4.z; r.w = o4.w + x4.w;
        *(float4*)&row[c] = r;
        lsum += r.x + r.y + r.z + r.w;
    }
    const float mean = block_sum256(lsum, red) * (1.f / HID);

    float lsq = 0.f;
    for (int c = tid * 4; c < HID; c += 1024) {
        const float4 r = *(const float4*)&row[c];
        const float dx = r.x - mean, dy = r.y - mean;
        const float dz = r.z - mean, dw = r.w - mean;
        lsq += dx * dx + dy * dy + dz * dz + dw * dw;
    }
    const float var  = block_sum256(lsq, red) * (1.f / HID);
    const float rstd = rsqrtf(var + 1e-5f);

    for (int c = tid * 4; c < HID; c += 1024) {
        const float4 r  = *(const float4*)&row[c];
        const float4 w4 = *(const float4*)(w + c);
        const float4 b4 = *(const float4*)(b + c);
        float4 y;
        y.x = (r.x - mean) * rstd * w4.x + b4.x;
        y.y = (r.y - mean) * rstd * w4.y + b4.y;
        y.z = (r.z - mean) * rstd * w4.z + b4.z;
        y.w = (r.w - mean) * rstd * w4.w + b4.w;
        *(float4*)(out + s * HID + c) = y;
    }
}

// ====================================================================
// launch
// ====================================================================
extern "C" void kernel_launch(void* const* d_in, const int* in_sizes, int n_in,
                              void* d_out, int out_size)
{
    const float* x   = (const float*)d_in[0];
    const float* Wq  = (const float*)d_in[1];
    const float* bq  = (const float*)d_in[2];
    const float* Wk  = (const float*)d_in[3];
    const float* bk  = (const float*)d_in[4];
    const float* Wv  = (const float*)d_in[5];
    const float* bv  = (const float*)d_in[6];
    const float* Wo  = (const float*)d_in[7];
    const float* bo  = (const float*)d_in[8];
    const float* lnw = (const float*)d_in[9];
    const float* lnb = (const float*)d_in[10];
    float* out = (float*)d_out;

    float *q, *k, *o, *rtab;
    __half *xhi, *whi, *qhi, *khi, *vhi;
    cudaGetSymbolAddress((void**)&q,    g_q);
    cudaGetSymbolAddress((void**)&k,    g_k);
    cudaGetSymbolAddress((void**)&o,    g_o);
    cudaGetSymbolAddress((void**)&rtab, g_rope);
    cudaGetSymbolAddress((void**)&xhi,  g_xhi);
    cudaGetSymbolAddress((void**)&whi,  g_whi);
    cudaGetSymbolAddress((void**)&qhi,  g_qhi);
    cudaGetSymbolAddress((void**)&khi,  g_khi);
    cudaGetSymbolAddress((void**)&vhi,  g_vhi);

    cudaFuncSetAttribute(gemm_f16,
                         cudaFuncAttributeMaxDynamicSharedMemorySize, GEMM_SMEM);
    cudaFuncSetAttribute(flash_tc,
                         cudaFuncAttributeMaxDynamicSharedMemorySize, FLASH_SMEM);

    const int N4 = SEQ * HID / 4;

    // ---- converts + rope table, one launch ----
    split6_kernel<<<dim3(N4 / 4 / 256, 6), 256>>>(x, Wq, Wk, Wv, Wo,
                                                  xhi, whi, rtab, N4);

    // ---- QKV projections (persistent; z==2 emits fp16 V) ----
    gemm_f16<<<GEMM_GRID, 128, GEMM_SMEM>>>(
        xhi, whi, bq, bk, bv, q, k, vhi, 768, 1);

    rope_split_kernel<<<SEQ, 1024>>>(q, k, rtab, qhi, khi);

    // ---- flash attention (64-row tiles; writes attn fp16 into xhi) ----
    flash_tc<<<dim3(SEQ / 64, NHEADS), 128, FLASH_SMEM>>>(
        qhi, khi, vhi, xhi);

    // ---- O projection (persistent; weights at slab 3) ----
    gemm_f16<<<GEMM_GRID, 128, GEMM_SMEM>>>(
        xhi, whi + 3 * (size_t)HID * HID, bo, bo, bo, o, o, vhi, 256, 0);

    ln_kernel<<<SEQ, 256>>>(o, x, lnw, lnb, out);
}

// round 16
// speedup vs baseline: 1.2656x; 1.2656x over previous
#include <cuda_runtime.h>
#include <cuda_fp16.h>
#include <math.h>
#include <stdint.h>

#define SEQ    2048
#define HID    2048
#define NHEADS 16
#define DH     128
#define ATT_SCALE 0.08838834764831845f   // 1/sqrt(128)

// ---------------- scratch (device globals: allocation-free) ----------------
__device__ float g_o[SEQ * HID];
__device__ float g_rope[SEQ * 64 * 2];      // cos/sin table
__device__ __half g_xhi[SEQ * HID];         // x / attn
__device__ __half g_whi[4 * HID * HID];     // weights
__device__ __half g_qhi[SEQ * HID];         // q (pre-rope then rotated in place)
__device__ __half g_khi[SEQ * HID];         // k (same)
__device__ __half g_vhi[SEQ * HID];

// ====================================================================
// common helpers
// ====================================================================
__device__ __forceinline__ uint32_t smem_u32(const void* p) {
    uint32_t a;
    asm("{ .reg .u64 t; cvta.to.shared.u64 t, %1; cvt.u32.u64 %0, t; }"
        : "=r"(a) : "l"(p));
    return a;
}

__device__ __forceinline__ uint32_t pack2h(__half a, __half b) {
    return (uint32_t)__half_as_ushort(a) |
           ((uint32_t)__half_as_ushort(b) << 16);
}

#define LDSM4(d0, d1, d2, d3, addr)                                        \
    asm volatile("ldmatrix.sync.aligned.m8n8.x4.shared.b16 "               \
                 "{%0,%1,%2,%3}, [%4];"                                    \
                 : "=r"(d0), "=r"(d1), "=r"(d2), "=r"(d3) : "r"(addr))

#define LDSM4T(d0, d1, d2, d3, addr)                                       \
    asm volatile("ldmatrix.sync.aligned.m8n8.x4.trans.shared.b16 "         \
                 "{%0,%1,%2,%3}, [%4];"                                    \
                 : "=r"(d0), "=r"(d1), "=r"(d2), "=r"(d3) : "r"(addr))

#define MMA_F16(acc, a, b)                                                 \
    asm volatile("mma.sync.aligned.m16n8k16.row.col.f32.f16.f16.f32 "      \
                 "{%0,%1,%2,%3}, {%4,%5,%6,%7}, {%8,%9}, {%0,%1,%2,%3};"   \
                 : "+f"((acc)[0]), "+f"((acc)[1]), "+f"((acc)[2]),         \
                   "+f"((acc)[3])                                          \
                 : "r"((a)[0]), "r"((a)[1]), "r"((a)[2]), "r"((a)[3]),     \
                   "r"((b)[0]), "r"((b)[1]))

#define CPA16(dst, src)                                                    \
    asm volatile("cp.async.cg.shared.global [%0], [%1], 16;"               \
                 :: "r"(dst), "l"(src))

// ====================================================================
// fp32 -> fp16 convert for x + 4 weights, plus rope table (y==5).
// ====================================================================
__global__ __launch_bounds__(256) void split6_kernel(
    const float* __restrict__ x,
    const float* __restrict__ wq, const float* __restrict__ wk,
    const float* __restrict__ wv, const float* __restrict__ wo,
    __half* __restrict__ xhi, __half* __restrict__ whi,
    float* __restrict__ rtab, int n4)
{
    const size_t W = (size_t)HID * HID;
    if (blockIdx.y == 5) {
        const int idx = blockIdx.x * 256 + threadIdx.x;
        if (idx < SEQ * 64) {
            const int s = idx >> 6;
            const int i = idx & 63;
            const float invf = (float)pow(10000.0, -(double)(2 * i) / 128.0);
            const float ang  = (float)s * invf;
            rtab[idx * 2]     = (float)cos((double)ang);
            rtab[idx * 2 + 1] = (float)sin((double)ang);
        }
        return;
    }
    const float* in;
    __half* hi;
    switch (blockIdx.y) {
        case 0:  in = x;  hi = xhi;         break;
        case 1:  in = wq; hi = whi;         break;
        case 2:  in = wk; hi = whi + W;     break;
        case 3:  in = wv; hi = whi + 2 * W; break;
        default: in = wo; hi = whi + 3 * W; break;
    }
    const int stride = gridDim.x * 256;
#pragma unroll
    for (int j = 0; j < 4; ++j) {
        const int i = blockIdx.x * 256 + threadIdx.x + j * stride;
        if (i < n4) {
            const float4 v = *(const float4*)(in + (size_t)i * 4);
            uint2 ph;
            ph.x = pack2h(__float2half_rn(v.x), __float2half_rn(v.y));
            ph.y = pack2h(__float2half_rn(v.z), __float2half_rn(v.w));
            *(uint2*)(hi + (size_t)i * 4) = ph;
        }
    }
}

// ====================================================================
// RoPE in place on fp16 q,k (each thread owns a full rotation pair)
// ====================================================================
__global__ __launch_bounds__(1024) void rope_inplace_kernel(
    __half* __restrict__ q16, __half* __restrict__ k16,
    const float* __restrict__ tab)
{
    const int s = blockIdx.x;
    const int t = threadIdx.x;
    const int h = t >> 6;
    const int i = t & 63;

    const float c  = tab[(s * 64 + i) * 2];
    const float sn = tab[(s * 64 + i) * 2 + 1];

    const int base = s * HID + h * DH + i;

    float a = __half2float(q16[base]), b = __half2float(q16[base + 64]);
    q16[base]      = __float2half_rn(a * c - b * sn);
    q16[base + 64] = __float2half_rn(b * c + a * sn);

    a = __half2float(k16[base]);  b = __half2float(k16[base + 64]);
    k16[base]      = __float2half_rn(a * c - b * sn);
    k16[base + 64] = __float2half_rn(b * c + a * sn);
}

// ====================================================================
// Pure fp16 persistent GEMM, BK=64, 256 threads (8 warps, 4x2),
// warp tile 32x64, 2-stage pipeline, 2 CTAs/SM, grid = 296 CTAs.
// vmode=1: all z write fp16 (q/k/v); vmode=0: fp32 + bias to Cf.
// ====================================================================
#define GBM 128
#define GBN 128
#define GBK 64
#define GKIT (HID / GBK)             // 32
#define PITCH 40
#define TILE_B (128 * PITCH * 2)     // 10240 (one 128x32-half sub-tile)
#define OFF_A 0
#define OFF_B (2 * TILE_B)
#define STAGE_B (4 * TILE_B)         // 40960
#define GEMM_SMEM (2 * STAGE_B)      // 81920
#define GEMM_GRID 296

__global__ __launch_bounds__(256, 2) void gemm_f16(
    const __half* __restrict__ Ah, const __half* __restrict__ Wbase,
    const float* __restrict__ b0, const float* __restrict__ b1,
    const float* __restrict__ b2,
    float* __restrict__ Cf,
    __half* __restrict__ H0, __half* __restrict__ H1,
    __half* __restrict__ H2, int ntiles, int vmode)
{
    extern __shared__ char sm[];
    const uint32_t sbase = smem_u32(sm);

    const int tid  = threadIdx.x;
    const int lane = tid & 31;
    const int wid  = tid >> 5;
    const int wm   = wid & 3;
    const int wn   = wid >> 2;

    const int lrow = tid >> 1;
    const int lcol = (tid & 1) * 16;
    const uint32_t sdst = (uint32_t)(lrow * (PITCH * 2) + lcol * 2);

    for (int tile = blockIdx.x; tile < ntiles; tile += GEMM_GRID) {
        const int z   = tile >> 8;
        const int rem = tile & 255;
        const int bm = (rem >> 4) * GBM;
        const int bn = (rem & 15) * GBN;

        const __half* Bh = Wbase + (size_t)z * HID * HID;
        const float* bias = (z == 0) ? b0 : (z == 1 ? b1 : b2);

        const __half* pA = Ah + (size_t)(bm + lrow) * HID + lcol;
        const __half* pB = Bh + (size_t)(bn + lrow) * HID + lcol;

        float acc[2][8][4];
#pragma unroll
        for (int mi = 0; mi < 2; ++mi)
#pragma unroll
            for (int nj = 0; nj < 8; ++nj)
#pragma unroll
                for (int c = 0; c < 4; ++c) acc[mi][nj][c] = 0.f;

        auto load_stage = [&](int kt, int buf) {
            const int k0 = kt * GBK;
            const uint32_t s = sbase + buf * STAGE_B + sdst;
#pragma unroll
            for (int ch = 0; ch < 2; ++ch) {
                CPA16(s + OFF_A + ch * TILE_B,      pA + k0 + ch * 32);
                CPA16(s + OFF_A + ch * TILE_B + 16, pA + k0 + ch * 32 + 8);
                CPA16(s + OFF_B + ch * TILE_B,      pB + k0 + ch * 32);
                CPA16(s + OFF_B + ch * TILE_B + 16, pB + k0 + ch * 32 + 8);
            }
        };

        load_stage(0, 0);
        asm volatile("cp.async.commit_group;");

        int buf = 0;
        for (int kt = 0; kt < GKIT; ++kt) {
            asm volatile("cp.async.wait_group 0;");
            __syncthreads();
            if (kt + 1 < GKIT) {
                load_stage(kt + 1, buf ^ 1);
                asm volatile("cp.async.commit_group;");
            }

            const uint32_t sS = sbase + buf * STAGE_B;

#pragma unroll
            for (int kk = 0; kk < 4; ++kk) {
                const uint32_t sA = sS + OFF_A + (kk >> 1) * TILE_B;
                const uint32_t sB = sS + OFF_B + (kk >> 1) * TILE_B;
                const int ksub = kk & 1;
                uint32_t a[2][4];
                const int r16 = lane & 15;
                const int ksel = lane >> 4;
#pragma unroll
                for (int mi = 0; mi < 2; ++mi) {
                    const uint32_t off =
                        (uint32_t)((wm * 32 + mi * 16 + r16) * (PITCH * 2) +
                                   (ksub * 2 + ksel) * 16);
                    LDSM4(a[mi][0], a[mi][1], a[mi][2], a[mi][3], sA + off);
                }
                const int q  = lane >> 3;
                const int rr = lane & 7;
#pragma unroll
                for (int a2 = 0; a2 < 4; ++a2) {
                    uint32_t bh[4];
                    const int row = wn * 64 + a2 * 16 + (q >> 1) * 8 + rr;
                    const uint32_t off =
                        (uint32_t)(row * (PITCH * 2) + (ksub * 2 + (q & 1)) * 16);
                    LDSM4(bh[0], bh[1], bh[2], bh[3], sB + off);
#pragma unroll
                    for (int mi = 0; mi < 2; ++mi) {
                        MMA_F16(acc[mi][a2 * 2],     a[mi], bh);
                        MMA_F16(acc[mi][a2 * 2 + 1], a[mi], bh + 2);
                    }
                }
            }
            buf ^= 1;
        }

        const int trow = lane >> 2;
        const int tcol = (lane & 3) * 2;
        if (vmode) {
            __half* H = (z == 0) ? H0 : (z == 1 ? H1 : H2);
#pragma unroll
            for (int mi = 0; mi < 2; ++mi) {
                const int r = bm + wm * 32 + mi * 16 + trow;
#pragma unroll
                for (int nj = 0; nj < 8; ++nj) {
                    const int c = bn + wn * 64 + nj * 8 + tcol;
                    const float bx = bias[c], by = bias[c + 1];
                    *(uint32_t*)(H + (size_t)r * HID + c) =
                        pack2h(__float2half_rn(acc[mi][nj][0] + bx),
                               __float2half_rn(acc[mi][nj][1] + by));
                    *(uint32_t*)(H + (size_t)(r + 8) * HID + c) =
                        pack2h(__float2half_rn(acc[mi][nj][2] + bx),
                               __float2half_rn(acc[mi][nj][3] + by));
                }
            }
        } else {
#pragma unroll
            for (int mi = 0; mi < 2; ++mi) {
                const int r = bm + wm * 32 + mi * 16 + trow;
#pragma unroll
                for (int nj = 0; nj < 8; ++nj) {
                    const int c = bn + wn * 64 + nj * 8 + tcol;
                    const float bx = bias[c], by = bias[c + 1];
                    float2 o;
                    o.x = acc[mi][nj][0] + bx; o.y = acc[mi][nj][1] + by;
                    *(float2*)(Cf + (size_t)r * HID + c) = o;
                    o.x = acc[mi][nj][2] + bx; o.y = acc[mi][nj][3] + by;
                    *(float2*)(Cf + (size_t)(r + 8) * HID + c) = o;
                }
            }
        }
    }
}

// ====================================================================
// Flash attention, pure fp16, 64-row q tiles, 128 threads (4 warps).
// Single-sync pipeline, long CTAs first. Writes attn fp16.
// ====================================================================
#define FP_B 272
#define QTILE_FB (64 * FP_B)         // 17408
#define KVTILE_FB (64 * FP_B)        // 17408
#define FKV0 QTILE_FB
#define FKSTG (2 * KVTILE_FB)        // 34816
#define FLASH_SMEM (FKV0 + 2 * FKSTG)   // 87040

__global__ __launch_bounds__(128) void flash_tc(
    const __half* __restrict__ qhi, const __half* __restrict__ khi,
    const __half* __restrict__ vhi, __half* __restrict__ Oh)
{
    extern __shared__ char sm[];
    const uint32_t sb = smem_u32(sm);
    const int h  = blockIdx.y;
    const int qb = gridDim.x - 1 - blockIdx.x;   // long CTAs first
    const int q0 = qb * 64;
    const int tid = threadIdx.x, lane = tid & 31, wm = tid >> 5;

    {
        const __half* ph = qhi + (size_t)q0 * HID + h * DH;
#pragma unroll
        for (int i = 0; i < 8; ++i) {
            const int idx = tid + i * 128, row = idx >> 4, c = idx & 15;
            CPA16(sb + (uint32_t)(row * FP_B + c * 16),
                  ph + (size_t)row * HID + c * 8);
        }
    }

    auto load_kv = [&](int t, int b) {
        const int j0 = t * 64;
        const uint32_t s = sb + FKV0 + b * FKSTG;
#pragma unroll
        for (int i = 0; i < 8; ++i) {
            const int idx = tid + i * 128, row = idx >> 4, c = idx & 15;
            const uint32_t d = (uint32_t)(row * FP_B + c * 16);
            const size_t g = (size_t)(j0 + row) * HID + h * DH + c * 8;
            CPA16(s + d,             khi + g);
            CPA16(s + KVTILE_FB + d, vhi + g);
        }
    };

    load_kv(0, 0);
    asm volatile("cp.async.commit_group;");

    float o[16][4];
#pragma unroll
    for (int f = 0; f < 16; ++f)
#pragma unroll
        for (int c = 0; c < 4; ++c) o[f][c] = 0.f;
    float m0 = -1e30f, m1 = -1e30f, l0 = 0.f, l1 = 0.f;

    const int ntiles = qb + 1;
    int buf = 0;
    for (int t = 0; t < ntiles; ++t) {
        asm volatile("cp.async.wait_group 0;");
        __syncthreads();
        if (t + 1 < ntiles) {
            load_kv(t + 1, buf ^ 1);
            asm volatile("cp.async.commit_group;");
        }

        const int j0 = t * 64;
        const uint32_t skh = sb + FKV0 + buf * FKSTG;
        const uint32_t svh = skh + KVTILE_FB;

        {
            float sc[8][4];
#pragma unroll
            for (int nj = 0; nj < 8; ++nj)
#pragma unroll
                for (int c = 0; c < 4; ++c) sc[nj][c] = 0.f;

            const int r16 = lane & 15, ksel = lane >> 4;
            const int qq = lane >> 3, rr = lane & 7;
#pragma unroll
            for (int kk = 0; kk < 8; ++kk) {
                uint32_t ah[4];
                const uint32_t aoff =
                    (uint32_t)((wm * 16 + r16) * FP_B + (kk * 2 + ksel) * 16);
                LDSM4(ah[0], ah[1], ah[2], ah[3], sb + aoff);
#pragma unroll
                for (int a2 = 0; a2 < 4; ++a2) {
                    uint32_t bh[4];
                    const uint32_t boff =
                        (uint32_t)((a2 * 16 + (qq >> 1) * 8 + rr) * FP_B +
                                   (kk * 2 + (qq & 1)) * 16);
                    LDSM4(bh[0], bh[1], bh[2], bh[3], skh + boff);
                    MMA_F16(sc[a2 * 2],     ah, bh);
                    MMA_F16(sc[a2 * 2 + 1], ah, bh + 2);
                }
            }

            const int r0g = q0 + wm * 16 + (lane >> 2);
            const bool needMask = (j0 + 63 > q0 + wm * 16);
#pragma unroll
            for (int nj = 0; nj < 8; ++nj) {
                const int c0 = j0 + nj * 8 + (lane & 3) * 2;
                sc[nj][0] *= ATT_SCALE; sc[nj][1] *= ATT_SCALE;
                sc[nj][2] *= ATT_SCALE; sc[nj][3] *= ATT_SCALE;
                if (needMask) {
                    if (c0     > r0g)     sc[nj][0] = -1e30f;
                    if (c0 + 1 > r0g)     sc[nj][1] = -1e30f;
                    if (c0     > r0g + 8) sc[nj][2] = -1e30f;
                    if (c0 + 1 > r0g + 8) sc[nj][3] = -1e30f;
                }
            }

            float mx0 = -1e30f, mx1 = -1e30f;
#pragma unroll
            for (int nj = 0; nj < 8; ++nj) {
                mx0 = fmaxf(mx0, fmaxf(sc[nj][0], sc[nj][1]));
                mx1 = fmaxf(mx1, fmaxf(sc[nj][2], sc[nj][3]));
            }
            mx0 = fmaxf(mx0, __shfl_xor_sync(0xffffffffu, mx0, 1));
            mx0 = fmaxf(mx0, __shfl_xor_sync(0xffffffffu, mx0, 2));
            mx1 = fmaxf(mx1, __shfl_xor_sync(0xffffffffu, mx1, 1));
            mx1 = fmaxf(mx1, __shfl_xor_sync(0xffffffffu, mx1, 2));
            const float mn0 = fmaxf(m0, mx0), mn1 = fmaxf(m1, mx1);
            const float al0 = __expf(m0 - mn0), al1 = __expf(m1 - mn1);
            float rs0 = 0.f, rs1 = 0.f;
#pragma unroll
            for (int nj = 0; nj < 8; ++nj) {
                sc[nj][0] = __expf(sc[nj][0] - mn0);
                sc[nj][1] = __expf(sc[nj][1] - mn0);
                sc[nj][2] = __expf(sc[nj][2] - mn1);
                sc[nj][3] = __expf(sc[nj][3] - mn1);
                rs0 += sc[nj][0] + sc[nj][1];
                rs1 += sc[nj][2] + sc[nj][3];
            }
            rs0 += __shfl_xor_sync(0xffffffffu, rs0, 1);
            rs0 += __shfl_xor_sync(0xffffffffu, rs0, 2);
            rs1 += __shfl_xor_sync(0xffffffffu, rs1, 1);
            rs1 += __shfl_xor_sync(0xffffffffu, rs1, 2);
            l0 = l0 * al0 + rs0; l1 = l1 * al1 + rs1;
            m0 = mn0; m1 = mn1;
#pragma unroll
            for (int f = 0; f < 16; ++f) {
                o[f][0] *= al0; o[f][1] *= al0;
                o[f][2] *= al1; o[f][3] *= al1;
            }

            uint32_t pfh[4][4];
#pragma unroll
            for (int tp = 0; tp < 4; ++tp) {
                const float* f0 = sc[2 * tp];
                const float* f1 = sc[2 * tp + 1];
#pragma unroll
                for (int half = 0; half < 2; ++half) {
                    const float a0 = half ? f1[0] : f0[0];
                    const float a1 = half ? f1[1] : f0[1];
                    const float a2 = half ? f1[2] : f0[2];
                    const float a3 = half ? f1[3] : f0[3];
                    pfh[tp][half * 2] =
                        pack2h(__float2half_rn(a0), __float2half_rn(a1));
                    pfh[tp][half * 2 + 1] =
                        pack2h(__float2half_rn(a2), __float2half_rn(a3));
                }
            }

            const int g = lane >> 3;
#pragma unroll
            for (int ks = 0; ks < 4; ++ks) {
                uint32_t vh[16][2];
                const int jrow = ks * 16 + (g & 1) * 8 + (lane & 7);
                const uint32_t cb = (uint32_t)((g >> 1) * 16);
#pragma unroll
                for (int n0 = 0; n0 < 8; ++n0) {
                    const uint32_t boff = (uint32_t)(jrow * FP_B + n0 * 32) + cb;
                    LDSM4T(vh[n0 * 2][0], vh[n0 * 2][1],
                           vh[n0 * 2 + 1][0], vh[n0 * 2 + 1][1], svh + boff);
                }
#pragma unroll
                for (int nf = 0; nf < 16; ++nf)
                    MMA_F16(o[nf], pfh[ks], vh[nf]);
            }
        }
        buf ^= 1;
    }

    const float i0 = 1.f / l0, i1 = 1.f / l1;
    const int r0g = q0 + wm * 16 + (lane >> 2);
#pragma unroll
    for (int nf = 0; nf < 16; ++nf) {
        const int col = h * DH + nf * 8 + (lane & 3) * 2;
        *(uint32_t*)(Oh + (size_t)r0g * HID + col) =
            pack2h(__float2half_rn(o[nf][0] * i0),
                   __float2half_rn(o[nf][1] * i0));
        *(uint32_t*)(Oh + (size_t)(r0g + 8) * HID + col) =
            pack2h(__float2half_rn(o[nf][2] * i1),
                   __float2half_rn(o[nf][3] * i1));
    }
}

// ====================================================================
// Residual + LayerNorm.
// ====================================================================
__device__ __forceinline__ float block_sum256(float v, float* red)
{
    __syncthreads();
    const int lane = threadIdx.x & 31;
    const int wp   = threadIdx.x >> 5;
#pragma unroll
    for (int o = 16; o; o >>= 1) v += __shfl_xor_sync(0xffffffffu, v, o);
    if (lane == 0) red[wp] = v;
    __syncthreads();
    if (wp == 0) {
        v = (lane < 8) ? red[lane] : 0.f;
#pragma unroll
        for (int o = 4; o; o >>= 1) v += __shfl_xor_sync(0xffffffffu, v, o);
        if (lane == 0) red[0] = v;
    }
    __syncthreads();
    return red[0];
}

__global__ __launch_bounds__(256) void ln_kernel(
    const float* __restrict__ O, const float* __restrict__ X,
    const float* __restrict__ w, const float* __restrict__ b,
    float* __restrict__ out)
{
    __shared__ float row[HID];
    __shared__ float red[8];
    const int s = blockIdx.x;
    const int tid = threadIdx.x;

    float lsum = 0.f;
    for (int c = tid * 4; c < HID; c += 1024) {
        const float4 o4 = *(const float4*)(O + s * HID + c);
        const float4 x4 = *(const float4*)(X + s * HID + c);
        float4 r;
        r.x = o4.x + x4.x; r.y = o4.y + x4.y;
        r.z = o4.z + x4.z; r.w = o4.w + x4.w;
        *(float4*)&row[c] = r;
        lsum += r.x + r.y + r.z + r.w;
    }
    const float mean = block_sum256(lsum, red) * (1.f / HID);

    float lsq = 0.f;
    for (int c = tid * 4; c < HID; c += 1024) {
        const float4 r = *(const float4*)&row[c];
        const float dx = r.x - mean, dy = r.y - mean;
        const float dz = r.z - mean, dw = r.w - mean;
        lsq += dx * dx + dy * dy + dz * dz + dw * dw;
    }
    const float var  = block_sum256(lsq, red) * (1.f / HID);
    const float rstd = rsqrtf(var + 1e-5f);

    for (int c = tid * 4; c < HID; c += 1024) {
        const float4 r  = *(const float4*)&row[c];
        const float4 w4 = *(const float4*)(w + c);
        const float4 b4 = *(const float4*)(b + c);
        float4 y;
        y.x = (r.x - mean) * rstd * w4.x + b4.x;
        y.y = (r.y - mean) * rstd * w4.y + b4.y;
        y.z = (r.z - mean) * rstd * w4.z + b4.z;
        y.w = (r.w - mean) * rstd * w4.w + b4.w;
        *(float4*)(out + s * HID + c) = y;
    }
}

// ====================================================================
// launch
// ====================================================================
extern "C" void kernel_launch(void* const* d_in, const int* in_sizes, int n_in,
                              void* d_out, int out_size)
{
    const float* x   = (const float*)d_in[0];
    const float* Wq  = (const float*)d_in[1];
    const float* bq  = (const float*)d_in[2];
    const float* Wk  = (const float*)d_in[3];
    const float* bk  = (const float*)d_in[4];
    const float* Wv  = (const float*)d_in[5];
    const float* bv  = (const float*)d_in[6];
    const float* Wo  = (const float*)d_in[7];
    const float* bo  = (const float*)d_in[8];
    const float* lnw = (const float*)d_in[9];
    const float* lnb = (const float*)d_in[10];
    float* out = (float*)d_out;

    float *o, *rtab;
    __half *xhi, *whi, *qhi, *khi, *vhi;
    cudaGetSymbolAddress((void**)&o,    g_o);
    cudaGetSymbolAddress((void**)&rtab, g_rope);
    cudaGetSymbolAddress((void**)&xhi,  g_xhi);
    cudaGetSymbolAddress((void**)&whi,  g_whi);
    cudaGetSymbolAddress((void**)&qhi,  g_qhi);
    cudaGetSymbolAddress((void**)&khi,  g_khi);
    cudaGetSymbolAddress((void**)&vhi,  g_vhi);

    cudaFuncSetAttribute(gemm_f16,
                         cudaFuncAttributeMaxDynamicSharedMemorySize, GEMM_SMEM);
    cudaFuncSetAttribute(flash_tc,
                         cudaFuncAttributeMaxDynamicSharedMemorySize, FLASH_SMEM);

    const int N4 = SEQ * HID / 4;

    // ---- converts + rope table, one launch ----
    split6_kernel<<<dim3(N4 / 4 / 256, 6), 256>>>(x, Wq, Wk, Wv, Wo,
                                                  xhi, whi, rtab, N4);

    // ---- QKV projections (persistent; q/k/v all emitted as fp16) ----
    gemm_f16<<<GEMM_GRID, 256, GEMM_SMEM>>>(
        xhi, whi, bq, bk, bv, o /*unused*/, qhi, khi, vhi, 768, 1);

    // ---- RoPE in place on fp16 q,k ----
    rope_inplace_kernel<<<SEQ, 1024>>>(qhi, khi, rtab);

    // ---- flash attention (64-row tiles; writes attn fp16 into xhi) ----
    flash_tc<<<dim3(SEQ / 64, NHEADS), 128, FLASH_SMEM>>>(
        qhi, khi, vhi, xhi);

    // ---- O projection (persistent; weights at slab 3; fp32 out) ----
    gemm_f16<<<GEMM_GRID, 256, GEMM_SMEM>>>(
        xhi, whi + 3 * (size_t)HID * HID, bo, bo, bo, o,
        qhi, khi, vhi /*unused*/, 256, 0);

    ln_kernel<<<SEQ, 256>>>(o, x, lnw, lnb, out);
}

// round 17
// speedup vs baseline: 1.2928x; 1.0215x over previous
#include <cuda_runtime.h>
#include <cuda_fp16.h>
#include <math.h>
#include <stdint.h>

#define SEQ    2048
#define HID    2048
#define NHEADS 16
#define DH     128
#define ATT_SCALE 0.08838834764831845f   // 1/sqrt(128)

// ---------------- scratch (device globals: allocation-free) ----------------
__device__ float g_o[SEQ * HID];
__device__ float g_rope[SEQ * 64 * 2];      // cos/sin table
__device__ __half g_xhi[SEQ * HID];         // x / attn
__device__ __half g_whi[4 * HID * HID];     // weights
__device__ __half g_qhi[SEQ * HID];         // q (pre-rope then rotated in place)
__device__ __half g_khi[SEQ * HID];         // k (same)
__device__ __half g_vhi[SEQ * HID];

// ====================================================================
// common helpers
// ====================================================================
__device__ __forceinline__ uint32_t smem_u32(const void* p) {
    uint32_t a;
    asm("{ .reg .u64 t; cvta.to.shared.u64 t, %1; cvt.u32.u64 %0, t; }"
        : "=r"(a) : "l"(p));
    return a;
}

__device__ __forceinline__ uint32_t pack2h(__half a, __half b) {
    return (uint32_t)__half_as_ushort(a) |
           ((uint32_t)__half_as_ushort(b) << 16);
}

#define LDSM4(d0, d1, d2, d3, addr)                                        \
    asm volatile("ldmatrix.sync.aligned.m8n8.x4.shared.b16 "               \
                 "{%0,%1,%2,%3}, [%4];"                                    \
                 : "=r"(d0), "=r"(d1), "=r"(d2), "=r"(d3) : "r"(addr))

#define LDSM4T(d0, d1, d2, d3, addr)                                       \
    asm volatile("ldmatrix.sync.aligned.m8n8.x4.trans.shared.b16 "         \
                 "{%0,%1,%2,%3}, [%4];"                                    \
                 : "=r"(d0), "=r"(d1), "=r"(d2), "=r"(d3) : "r"(addr))

#define MMA_F16(acc, a, b)                                                 \
    asm volatile("mma.sync.aligned.m16n8k16.row.col.f32.f16.f16.f32 "      \
                 "{%0,%1,%2,%3}, {%4,%5,%6,%7}, {%8,%9}, {%0,%1,%2,%3};"   \
                 : "+f"((acc)[0]), "+f"((acc)[1]), "+f"((acc)[2]),         \
                   "+f"((acc)[3])                                          \
                 : "r"((a)[0]), "r"((a)[1]), "r"((a)[2]), "r"((a)[3]),     \
                   "r"((b)[0]), "r"((b)[1]))

#define CPA16(dst, src)                                                    \
    asm volatile("cp.async.cg.shared.global [%0], [%1], 16;"               \
                 :: "r"(dst), "l"(src))

// ====================================================================
// fp32 -> fp16 convert for x + 4 weights, plus rope table (y==5).
// ====================================================================
__global__ __launch_bounds__(256) void split6_kernel(
    const float* __restrict__ x,
    const float* __restrict__ wq, const float* __restrict__ wk,
    const float* __restrict__ wv, const float* __restrict__ wo,
    __half* __restrict__ xhi, __half* __restrict__ whi,
    float* __restrict__ rtab, int n4)
{
    const size_t W = (size_t)HID * HID;
    if (blockIdx.y == 5) {
        const int idx = blockIdx.x * 256 + threadIdx.x;
        if (idx < SEQ * 64) {
            const int s = idx >> 6;
            const int i = idx & 63;
            const float invf = (float)pow(10000.0, -(double)(2 * i) / 128.0);
            const float ang  = (float)s * invf;
            rtab[idx * 2]     = (float)cos((double)ang);
            rtab[idx * 2 + 1] = (float)sin((double)ang);
        }
        return;
    }
    const float* in;
    __half* hi;
    switch (blockIdx.y) {
        case 0:  in = x;  hi = xhi;         break;
        case 1:  in = wq; hi = whi;         break;
        case 2:  in = wk; hi = whi + W;     break;
        case 3:  in = wv; hi = whi + 2 * W; break;
        default: in = wo; hi = whi + 3 * W; break;
    }
    const int stride = gridDim.x * 256;
#pragma unroll
    for (int j = 0; j < 4; ++j) {
        const int i = blockIdx.x * 256 + threadIdx.x + j * stride;
        if (i < n4) {
            const float4 v = *(const float4*)(in + (size_t)i * 4);
            uint2 ph;
            ph.x = pack2h(__float2half_rn(v.x), __float2half_rn(v.y));
            ph.y = pack2h(__float2half_rn(v.z), __float2half_rn(v.w));
            *(uint2*)(hi + (size_t)i * 4) = ph;
        }
    }
}

// ====================================================================
// RoPE in place on fp16 q,k (each thread owns a full rotation pair)
// ====================================================================
__global__ __launch_bounds__(1024) void rope_inplace_kernel(
    __half* __restrict__ q16, __half* __restrict__ k16,
    const float* __restrict__ tab)
{
    const int s = blockIdx.x;
    const int t = threadIdx.x;
    const int h = t >> 6;
    const int i = t & 63;

    const float c  = tab[(s * 64 + i) * 2];
    const float sn = tab[(s * 64 + i) * 2 + 1];

    const int base = s * HID + h * DH + i;

    float a = __half2float(q16[base]), b = __half2float(q16[base + 64]);
    q16[base]      = __float2half_rn(a * c - b * sn);
    q16[base + 64] = __float2half_rn(b * c + a * sn);

    a = __half2float(k16[base]);  b = __half2float(k16[base + 64]);
    k16[base]      = __float2half_rn(a * c - b * sn);
    k16[base + 64] = __float2half_rn(b * c + a * sn);
}

// ====================================================================
// Pure fp16 persistent GEMM, BK=32, 3-stage pipeline, 256 threads
// (8 warps, 4x2, warp tile 32x64), 2 CTAs/SM, grid = 296 CTAs.
// vmode=1: all z write fp16 (q/k/v); vmode=0: fp32 + bias to Cf.
// ====================================================================
#define GBM 128
#define GBN 128
#define GBK 32
#define GKIT (HID / GBK)             // 64
#define PITCH 40
#define TILE_B (128 * PITCH * 2)     // 10240
#define OFF_A 0
#define OFF_B TILE_B
#define STAGE_B (2 * TILE_B)         // 20480
#define GEMM_SMEM (3 * STAGE_B)      // 61440 (3 stages)
#define GEMM_GRID 296

__global__ __launch_bounds__(256, 2) void gemm_f16(
    const __half* __restrict__ Ah, const __half* __restrict__ Wbase,
    const float* __restrict__ b0, const float* __restrict__ b1,
    const float* __restrict__ b2,
    float* __restrict__ Cf,
    __half* __restrict__ H0, __half* __restrict__ H1,
    __half* __restrict__ H2, int ntiles, int vmode)
{
    extern __shared__ char sm[];
    const uint32_t sbase = smem_u32(sm);

    const int tid  = threadIdx.x;
    const int lane = tid & 31;
    const int wid  = tid >> 5;
    const int wm   = wid & 3;
    const int wn   = wid >> 2;

    const int lrow = tid >> 1;
    const int lcol = (tid & 1) * 16;
    const uint32_t sdst = (uint32_t)(lrow * (PITCH * 2) + lcol * 2);

    for (int tile = blockIdx.x; tile < ntiles; tile += GEMM_GRID) {
        __syncthreads();   // all warps done with previous tile's buffers

        const int z   = tile >> 8;
        const int rem = tile & 255;
        const int bm = (rem >> 4) * GBM;
        const int bn = (rem & 15) * GBN;

        const __half* Bh = Wbase + (size_t)z * HID * HID;
        const float* bias = (z == 0) ? b0 : (z == 1 ? b1 : b2);

        const __half* pA = Ah + (size_t)(bm + lrow) * HID + lcol;
        const __half* pB = Bh + (size_t)(bn + lrow) * HID + lcol;

        float acc[2][8][4];
#pragma unroll
        for (int mi = 0; mi < 2; ++mi)
#pragma unroll
            for (int nj = 0; nj < 8; ++nj)
#pragma unroll
                for (int c = 0; c < 4; ++c) acc[mi][nj][c] = 0.f;

        auto load_stage = [&](int kt, int buf) {
            const int k0 = kt * GBK;
            const uint32_t s = sbase + buf * STAGE_B + sdst;
            CPA16(s + OFF_A,      pA + k0);
            CPA16(s + OFF_A + 16, pA + k0 + 8);
            CPA16(s + OFF_B,      pB + k0);
            CPA16(s + OFF_B + 16, pB + k0 + 8);
        };

        load_stage(0, 0);
        asm volatile("cp.async.commit_group;");
        load_stage(1, 1);
        asm volatile("cp.async.commit_group;");

        for (int kt = 0; kt < GKIT; ++kt) {
            const int buf = kt % 3;
            asm volatile("cp.async.wait_group 1;");   // stage kt resident
            __syncthreads();
            if (kt + 2 < GKIT) {
                load_stage(kt + 2, (kt + 2) % 3);
                asm volatile("cp.async.commit_group;");
            } else {
                asm volatile("cp.async.commit_group;");   // keep count valid
            }

            const uint32_t sA = sbase + buf * STAGE_B + OFF_A;
            const uint32_t sB = sbase + buf * STAGE_B + OFF_B;

#pragma unroll
            for (int kk = 0; kk < 2; ++kk) {
                uint32_t a[2][4];
                const int r16 = lane & 15;
                const int ksel = lane >> 4;
#pragma unroll
                for (int mi = 0; mi < 2; ++mi) {
                    const uint32_t off =
                        (uint32_t)((wm * 32 + mi * 16 + r16) * (PITCH * 2) +
                                   (kk * 2 + ksel) * 16);
                    LDSM4(a[mi][0], a[mi][1], a[mi][2], a[mi][3], sA + off);
                }
                const int q  = lane >> 3;
                const int rr = lane & 7;
#pragma unroll
                for (int a2 = 0; a2 < 4; ++a2) {
                    uint32_t bh[4];
                    const int row = wn * 64 + a2 * 16 + (q >> 1) * 8 + rr;
                    const uint32_t off =
                        (uint32_t)(row * (PITCH * 2) + (kk * 2 + (q & 1)) * 16);
                    LDSM4(bh[0], bh[1], bh[2], bh[3], sB + off);
#pragma unroll
                    for (int mi = 0; mi < 2; ++mi) {
                        MMA_F16(acc[mi][a2 * 2],     a[mi], bh);
                        MMA_F16(acc[mi][a2 * 2 + 1], a[mi], bh + 2);
                    }
                }
            }
        }

        const int trow = lane >> 2;
        const int tcol = (lane & 3) * 2;
        if (vmode) {
            __half* H = (z == 0) ? H0 : (z == 1 ? H1 : H2);
#pragma unroll
            for (int mi = 0; mi < 2; ++mi) {
                const int r = bm + wm * 32 + mi * 16 + trow;
#pragma unroll
                for (int nj = 0; nj < 8; ++nj) {
                    const int c = bn + wn * 64 + nj * 8 + tcol;
                    const float bx = bias[c], by = bias[c + 1];
                    *(uint32_t*)(H + (size_t)r * HID + c) =
                        pack2h(__float2half_rn(acc[mi][nj][0] + bx),
                               __float2half_rn(acc[mi][nj][1] + by));
                    *(uint32_t*)(H + (size_t)(r + 8) * HID + c) =
                        pack2h(__float2half_rn(acc[mi][nj][2] + bx),
                               __float2half_rn(acc[mi][nj][3] + by));
                }
            }
        } else {
#pragma unroll
            for (int mi = 0; mi < 2; ++mi) {
                const int r = bm + wm * 32 + mi * 16 + trow;
#pragma unroll
                for (int nj = 0; nj < 8; ++nj) {
                    const int c = bn + wn * 64 + nj * 8 + tcol;
                    const float bx = bias[c], by = bias[c + 1];
                    float2 o;
                    o.x = acc[mi][nj][0] + bx; o.y = acc[mi][nj][1] + by;
                    *(float2*)(Cf + (size_t)r * HID + c) = o;
                    o.x = acc[mi][nj][2] + bx; o.y = acc[mi][nj][3] + by;
                    *(float2*)(Cf + (size_t)(r + 8) * HID + c) = o;
                }
            }
        }
    }
}

// ====================================================================
// Flash attention, pure fp16, 64-row q tiles, 128 threads (4 warps).
// Single-sync pipeline, long CTAs first. Writes attn fp16.
// ====================================================================
#define FP_B 272
#define QTILE_FB (64 * FP_B)         // 17408
#define KVTILE_FB (64 * FP_B)        // 17408
#define FKV0 QTILE_FB
#define FKSTG (2 * KVTILE_FB)        // 34816
#define FLASH_SMEM (FKV0 + 2 * FKSTG)   // 87040

__global__ __launch_bounds__(128) void flash_tc(
    const __half* __restrict__ qhi, const __half* __restrict__ khi,
    const __half* __restrict__ vhi, __half* __restrict__ Oh)
{
    extern __shared__ char sm[];
    const uint32_t sb = smem_u32(sm);
    const int h  = blockIdx.y;
    const int qb = gridDim.x - 1 - blockIdx.x;   // long CTAs first
    const int q0 = qb * 64;
    const int tid = threadIdx.x, lane = tid & 31, wm = tid >> 5;

    {
        const __half* ph = qhi + (size_t)q0 * HID + h * DH;
#pragma unroll
        for (int i = 0; i < 8; ++i) {
            const int idx = tid + i * 128, row = idx >> 4, c = idx & 15;
            CPA16(sb + (uint32_t)(row * FP_B + c * 16),
                  ph + (size_t)row * HID + c * 8);
        }
    }

    auto load_kv = [&](int t, int b) {
        const int j0 = t * 64;
        const uint32_t s = sb + FKV0 + b * FKSTG;
#pragma unroll
        for (int i = 0; i < 8; ++i) {
            const int idx = tid + i * 128, row = idx >> 4, c = idx & 15;
            const uint32_t d = (uint32_t)(row * FP_B + c * 16);
            const size_t g = (size_t)(j0 + row) * HID + h * DH + c * 8;
            CPA16(s + d,             khi + g);
            CPA16(s + KVTILE_FB + d, vhi + g);
        }
    };

    load_kv(0, 0);
    asm volatile("cp.async.commit_group;");

    float o[16][4];
#pragma unroll
    for (int f = 0; f < 16; ++f)
#pragma unroll
        for (int c = 0; c < 4; ++c) o[f][c] = 0.f;
    float m0 = -1e30f, m1 = -1e30f, l0 = 0.f, l1 = 0.f;

    const int ntiles = qb + 1;
    int buf = 0;
    for (int t = 0; t < ntiles; ++t) {
        asm volatile("cp.async.wait_group 0;");
        __syncthreads();
        if (t + 1 < ntiles) {
            load_kv(t + 1, buf ^ 1);
            asm volatile("cp.async.commit_group;");
        }

        const int j0 = t * 64;
        const uint32_t skh = sb + FKV0 + buf * FKSTG;
        const uint32_t svh = skh + KVTILE_FB;

        {
            float sc[8][4];
#pragma unroll
            for (int nj = 0; nj < 8; ++nj)
#pragma unroll
                for (int c = 0; c < 4; ++c) sc[nj][c] = 0.f;

            const int r16 = lane & 15, ksel = lane >> 4;
            const int qq = lane >> 3, rr = lane & 7;
#pragma unroll
            for (int kk = 0; kk < 8; ++kk) {
                uint32_t ah[4];
                const uint32_t aoff =
                    (uint32_t)((wm * 16 + r16) * FP_B + (kk * 2 + ksel) * 16);
                LDSM4(ah[0], ah[1], ah[2], ah[3], sb + aoff);
#pragma unroll
                for (int a2 = 0; a2 < 4; ++a2) {
                    uint32_t bh[4];
                    const uint32_t boff =
                        (uint32_t)((a2 * 16 + (qq >> 1) * 8 + rr) * FP_B +
                                   (kk * 2 + (qq & 1)) * 16);
                    LDSM4(bh[0], bh[1], bh[2], bh[3], skh + boff);
                    MMA_F16(sc[a2 * 2],     ah, bh);
                    MMA_F16(sc[a2 * 2 + 1], ah, bh + 2);
                }
            }

            const int r0g = q0 + wm * 16 + (lane >> 2);
            const bool needMask = (j0 + 63 > q0 + wm * 16);
#pragma unroll
            for (int nj = 0; nj < 8; ++nj) {
                const int c0 = j0 + nj * 8 + (lane & 3) * 2;
                sc[nj][0] *= ATT_SCALE; sc[nj][1] *= ATT_SCALE;
                sc[nj][2] *= ATT_SCALE; sc[nj][3] *= ATT_SCALE;
                if (needMask) {
                    if (c0     > r0g)     sc[nj][0] = -1e30f;
                    if (c0 + 1 > r0g)     sc[nj][1] = -1e30f;
                    if (c0     > r0g + 8) sc[nj][2] = -1e30f;
                    if (c0 + 1 > r0g + 8) sc[nj][3] = -1e30f;
                }
            }

            float mx0 = -1e30f, mx1 = -1e30f;
#pragma unroll
            for (int nj = 0; nj < 8; ++nj) {
                mx0 = fmaxf(mx0, fmaxf(sc[nj][0], sc[nj][1]));
                mx1 = fmaxf(mx1, fmaxf(sc[nj][2], sc[nj][3]));
            }
            mx0 = fmaxf(mx0, __shfl_xor_sync(0xffffffffu, mx0, 1));
            mx0 = fmaxf(mx0, __shfl_xor_sync(0xffffffffu, mx0, 2));
            mx1 = fmaxf(mx1, __shfl_xor_sync(0xffffffffu, mx1, 1));
            mx1 = fmaxf(mx1, __shfl_xor_sync(0xffffffffu, mx1, 2));
            const float mn0 = fmaxf(m0, mx0), mn1 = fmaxf(m1, mx1);
            const float al0 = __expf(m0 - mn0), al1 = __expf(m1 - mn1);
            float rs0 = 0.f, rs1 = 0.f;
#pragma unroll
            for (int nj = 0; nj < 8; ++nj) {
                sc[nj][0] = __expf(sc[nj][0] - mn0);
                sc[nj][1] = __expf(sc[nj][1] - mn0);
                sc[nj][2] = __expf(sc[nj][2] - mn1);
                sc[nj][3] = __expf(sc[nj][3] - mn1);
                rs0 += sc[nj][0] + sc[nj][1];
                rs1 += sc[nj][2] + sc[nj][3];
            }
            rs0 += __shfl_xor_sync(0xffffffffu, rs0, 1);
            rs0 += __shfl_xor_sync(0xffffffffu, rs0, 2);
            rs1 += __shfl_xor_sync(0xffffffffu, rs1, 1);
            rs1 += __shfl_xor_sync(0xffffffffu, rs1, 2);
            l0 = l0 * al0 + rs0; l1 = l1 * al1 + rs1;
            m0 = mn0; m1 = mn1;
#pragma unroll
            for (int f = 0; f < 16; ++f) {
                o[f][0] *= al0; o[f][1] *= al0;
                o[f][2] *= al1; o[f][3] *= al1;
            }

            uint32_t pfh[4][4];
#pragma unroll
            for (int tp = 0; tp < 4; ++tp) {
                const float* f0 = sc[2 * tp];
                const float* f1 = sc[2 * tp + 1];
#pragma unroll
                for (int half = 0; half < 2; ++half) {
                    const float a0 = half ? f1[0] : f0[0];
                    const float a1 = half ? f1[1] : f0[1];
                    const float a2 = half ? f1[2] : f0[2];
                    const float a3 = half ? f1[3] : f0[3];
                    pfh[tp][half * 2] =
                        pack2h(__float2half_rn(a0), __float2half_rn(a1));
                    pfh[tp][half * 2 + 1] =
                        pack2h(__float2half_rn(a2), __float2half_rn(a3));
                }
            }

            const int g = lane >> 3;
#pragma unroll
            for (int ks = 0; ks < 4; ++ks) {
                uint32_t vh[16][2];
                const int jrow = ks * 16 + (g & 1) * 8 + (lane & 7);
                const uint32_t cb = (uint32_t)((g >> 1) * 16);
#pragma unroll
                for (int n0 = 0; n0 < 8; ++n0) {
                    const uint32_t boff = (uint32_t)(jrow * FP_B + n0 * 32) + cb;
                    LDSM4T(vh[n0 * 2][0], vh[n0 * 2][1],
                           vh[n0 * 2 + 1][0], vh[n0 * 2 + 1][1], svh + boff);
                }
#pragma unroll
                for (int nf = 0; nf < 16; ++nf)
                    MMA_F16(o[nf], pfh[ks], vh[nf]);
            }
        }
        buf ^= 1;
    }

    const float i0 = 1.f / l0, i1 = 1.f / l1;
    const int r0g = q0 + wm * 16 + (lane >> 2);
#pragma unroll
    for (int nf = 0; nf < 16; ++nf) {
        const int col = h * DH + nf * 8 + (lane & 3) * 2;
        *(uint32_t*)(Oh + (size_t)r0g * HID + col) =
            pack2h(__float2half_rn(o[nf][0] * i0),
                   __float2half_rn(o[nf][1] * i0));
        *(uint32_t*)(Oh + (size_t)(r0g + 8) * HID + col) =
            pack2h(__float2half_rn(o[nf][2] * i1),
                   __float2half_rn(o[nf][3] * i1));
    }
}

// ====================================================================
// Residual + LayerNorm.
// ====================================================================
__device__ __forceinline__ float block_sum256(float v, float* red)
{
    __syncthreads();
    const int lane = threadIdx.x & 31;
    const int wp   = threadIdx.x >> 5;
#pragma unroll
    for (int o = 16; o; o >>= 1) v += __shfl_xor_sync(0xffffffffu, v, o);
    if (lane == 0) red[wp] = v;
    __syncthreads();
    if (wp == 0) {
        v = (lane < 8) ? red[lane] : 0.f;
#pragma unroll
        for (int o = 4; o; o >>= 1) v += __shfl_xor_sync(0xffffffffu, v, o);
        if (lane == 0) red[0] = v;
    }
    __syncthreads();
    return red[0];
}

__global__ __launch_bounds__(256) void ln_kernel(
    const float* __restrict__ O, const float* __restrict__ X,
    const float* __restrict__ w, const float* __restrict__ b,
    float* __restrict__ out)
{
    __shared__ float row[HID];
    __shared__ float red[8];
    const int s = blockIdx.x;
    const int tid = threadIdx.x;

    float lsum = 0.f;
    for (int c = tid * 4; c < HID; c += 1024) {
        const float4 o4 = *(const float4*)(O + s * HID + c);
        const float4 x4 = *(const float4*)(X + s * HID + c);
        float4 r;
        r.x = o4.x + x4.x; r.y = o4.y + x4.y;
        r.z = o4.z + x4.z; r.w = o4.w + x4.w;
        *(float4*)&row[c] = r;
        lsum += r.x + r.y + r.z + r.w;
    }
    const float mean = block_sum256(lsum, red) * (1.f / HID);

    float lsq = 0.f;
    for (int c = tid * 4; c < HID; c += 1024) {
        const float4 r = *(const float4*)&row[c];
        const float dx = r.x - mean, dy = r.y - mean;
        const float dz = r.z - mean, dw = r.w - mean;
        lsq += dx * dx + dy * dy + dz * dz + dw * dw;
    }
    const float var  = block_sum256(lsq, red) * (1.f / HID);
    const float rstd = rsqrtf(var + 1e-5f);

    for (int c = tid * 4; c < HID; c += 1024) {
        const float4 r  = *(const float4*)&row[c];
        const float4 w4 = *(const float4*)(w + c);
        const float4 b4 = *(const float4*)(b + c);
        float4 y;
        y.x = (r.x - mean) * rstd * w4.x + b4.x;
        y.y = (r.y - mean) * rstd * w4.y + b4.y;
        y.z = (r.z - mean) * rstd * w4.z + b4.z;
        y.w = (r.w - mean) * rstd * w4.w + b4.w;
        *(float4*)(out + s * HID + c) = y;
    }
}

// ====================================================================
// launch
// ====================================================================
extern "C" void kernel_launch(void* const* d_in, const int* in_sizes, int n_in,
                              void* d_out, int out_size)
{
    const float* x   = (const float*)d_in[0];
    const float* Wq  = (const float*)d_in[1];
    const float* bq  = (const float*)d_in[2];
    const float* Wk  = (const float*)d_in[3];
    const float* bk  = (const float*)d_in[4];
    const float* Wv  = (const float*)d_in[5];
    const float* bv  = (const float*)d_in[6];
    const float* Wo  = (const float*)d_in[7];
    const float* bo  = (const float*)d_in[8];
    const float* lnw = (const float*)d_in[9];
    const float* lnb = (const float*)d_in[10];
    float* out = (float*)d_out;

    float *o, *rtab;
    __half *xhi, *whi, *qhi, *khi, *vhi;
    cudaGetSymbolAddress((void**)&o,    g_o);
    cudaGetSymbolAddress((void**)&rtab, g_rope);
    cudaGetSymbolAddress((void**)&xhi,  g_xhi);
    cudaGetSymbolAddress((void**)&whi,  g_whi);
    cudaGetSymbolAddress((void**)&qhi,  g_qhi);
    cudaGetSymbolAddress((void**)&khi,  g_khi);
    cudaGetSymbolAddress((void**)&vhi,  g_vhi);

    cudaFuncSetAttribute(gemm_f16,
                         cudaFuncAttributeMaxDynamicSharedMemorySize, GEMM_SMEM);
    cudaFuncSetAttribute(flash_tc,
                         cudaFuncAttributeMaxDynamicSharedMemorySize, FLASH_SMEM);

    const int N4 = SEQ * HID / 4;

    // ---- converts + rope table, one launch ----
    split6_kernel<<<dim3(N4 / 4 / 256, 6), 256>>>(x, Wq, Wk, Wv, Wo,
                                                  xhi, whi, rtab, N4);

    // ---- QKV projections (persistent; q/k/v all emitted as fp16) ----
    gemm_f16<<<GEMM_GRID, 256, GEMM_SMEM>>>(
        xhi, whi, bq, bk, bv, o /*unused*/, qhi, khi, vhi, 768, 1);

    // ---- RoPE in place on fp16 q,k ----
    rope_inplace_kernel<<<SEQ, 1024>>>(qhi, khi, rtab);

    // ---- flash attention (64-row tiles; writes attn fp16 into xhi) ----
    flash_tc<<<dim3(SEQ / 64, NHEADS), 128, FLASH_SMEM>>>(
        qhi, khi, vhi, xhi);

    // ---- O projection (persistent; weights at slab 3; fp32 out) ----
    gemm_f16<<<GEMM_GRID, 256, GEMM_SMEM>>>(
        xhi, whi + 3 * (size_t)HID * HID, bo, bo, bo, o,
        qhi, khi, vhi /*unused*/, 256, 0);

    ln_kernel<<<SEQ, 256>>>(o, x, lnw, lnb, out);
}